// round 1
// baseline (speedup 1.0000x reference)
#include <cuda_runtime.h>
#include <cstdint>

// ---------------- problem constants ----------------
#define NCAND   1600          // 100 i-steps x 16 zero-points
#define TPB     256
#define GRID    296           // 2 blocks/SM on 148 SMs -> single wave
#define NWARPS  (GRID * (TPB / 32))   // 2368
#define C_MAGIC 12582912.0f   // 1.5 * 2^23 : round-to-nearest-even trick
#define EPS_F32 1.1920928955078125e-07f

// ---------------- device scratch (no allocs allowed) ----------------
__device__ unsigned int g_min_enc;
__device__ unsigned int g_max_enc;
__device__ float4 g_params[NCAND];            // {inv_s, -s, lo(-z), hi(15-z)}
__device__ float  g_bmin[NCAND];
__device__ float  g_bmax[NCAND];
__device__ float  g_partials[(size_t)NWARPS * NCAND];  // [warp][cand]
__device__ double g_scores[NCAND];

// ---------------- helpers ----------------
__device__ __forceinline__ unsigned enc_f32(float f) {
    unsigned u = __float_as_uint(f);
    return (u & 0x80000000u) ? ~u : (u | 0x80000000u);
}
__device__ __forceinline__ float dec_f32(unsigned e) {
    unsigned u = (e & 0x80000000u) ? (e ^ 0x80000000u) : ~e;
    return __uint_as_float(u);
}

// ---------------- kernel 0: init sentinels ----------------
__global__ void k_init() {
    g_min_enc = 0xFFFFFFFFu;
    g_max_enc = 0u;
}

// ---------------- kernel 1: global min/max ----------------
__global__ void k_minmax(const float* __restrict__ x, int n) {
    int tid = blockIdx.x * TPB + threadIdx.x;
    int stride = GRID * TPB;
    float lmin =  3.4e38f, lmax = -3.4e38f;
    int n4 = n >> 2;
    const float4* x4 = (const float4*)x;
    for (int p = tid; p < n4; p += stride) {
        float4 v = __ldg(x4 + p);
        lmin = fminf(lmin, fminf(fminf(v.x, v.y), fminf(v.z, v.w)));
        lmax = fmaxf(lmax, fmaxf(fmaxf(v.x, v.y), fmaxf(v.z, v.w)));
    }
    int r = n & 3;
    if (tid < r) {
        float v = x[n - r + tid];
        lmin = fminf(lmin, v);
        lmax = fmaxf(lmax, v);
    }
    unsigned emin = enc_f32(lmin);
    unsigned emax = enc_f32(lmax);
    emin = __reduce_min_sync(0xFFFFFFFFu, emin);
    emax = __reduce_max_sync(0xFFFFFFFFu, emax);
    if ((threadIdx.x & 31) == 0) {
        atomicMin(&g_min_enc, emin);
        atomicMax(&g_max_enc, emax);
    }
}

// ---------------- kernel 2: build 1600 candidate params ----------------
__global__ void k_candidates() {
    int c = blockIdx.x * blockDim.x + threadIdx.x;
    if (c >= NCAND) return;
    float x_min = dec_f32(g_min_enc);
    float x_max = dec_f32(g_max_enc);
    float xrange = x_max - x_min;

    int i = c / 16 + 1;        // 1..100
    int j = c % 16;            // zero-point candidate
    float fi = (float)i;
    float zj = (float)j;

    float tmp_max   = __fdiv_rn(xrange, 100.0f) * fi;
    float tmp_delta = __fdiv_rn(tmp_max, 15.0f);

    float new_min = fmaxf(-(zj * tmp_delta), x_min);
    float new_max = fminf(tmp_max - zj * tmp_delta, x_max);
    float min_neg = fminf(new_min, 0.0f);
    float max_pos = fmaxf(new_max, 0.0f);
    float scale = fmaxf(__fdiv_rn(max_pos - min_neg, 15.0f), EPS_F32);
    float zp = fminf(fmaxf(0.0f - rintf(__fdiv_rn(min_neg, scale)), 0.0f), 15.0f);

    float4 p;
    p.x = __fdiv_rn(1.0f, scale);  // inv_s
    p.y = -scale;                  // -s  (err = x - q*s via fma(q, -s, x))
    p.z = -zp;                     // clip low  (round(x/s) clipped to [-z, 15-z])
    p.w = 15.0f - zp;              // clip high
    g_params[c] = p;
    g_bmin[c] = new_min;
    g_bmax[c] = new_max;
}

// ---------------- kernel 3: brute-force MSE over all candidates ----------------
__device__ __forceinline__ void eval_one(float xv, const float4& pa, float& acc) {
    float t = fmaf(xv, pa.x, C_MAGIC);   // magic round-to-nearest-even of x*inv_s
    float q = t - C_MAGIC;               // exact for |r| <= 16 (Sterbenz)
    q = fmaxf(q, pa.z);
    q = fminf(q, pa.w);
    float e = fmaf(q, pa.y, xv);         // x - q*s, single rounding
    acc = fmaf(e, e, acc);
}

__global__ void __launch_bounds__(TPB, 2) k_mse(const float* __restrict__ x, int n) {
    __shared__ float4 sp[NCAND];
    for (int k = threadIdx.x; k < NCAND; k += TPB) sp[k] = g_params[k];
    __syncthreads();

    int tid    = blockIdx.x * TPB + threadIdx.x;
    int stride = GRID * TPB;
    int lane   = threadIdx.x & 31;
    int warpG  = blockIdx.x * (TPB / 32) + (threadIdx.x >> 5);
    int n4 = n >> 2;
    int r  = n & 3;
    const float4* x4 = (const float4*)x;

    for (int g = 0; g < 100; ++g) {
        float acc[16];
        #pragma unroll
        for (int c = 0; c < 16; ++c) acc[c] = 0.0f;

        for (int p = tid; p < n4; p += stride) {
            float4 xv = __ldg(x4 + p);
            #pragma unroll
            for (int c = 0; c < 16; ++c) {
                float4 pa = sp[g * 16 + c];
                eval_one(xv.x, pa, acc[c]);
                eval_one(xv.y, pa, acc[c]);
                eval_one(xv.z, pa, acc[c]);
                eval_one(xv.w, pa, acc[c]);
            }
        }
        if (r && tid < r) {
            float xv = x[n - r + tid];
            #pragma unroll
            for (int c = 0; c < 16; ++c) {
                float4 pa = sp[g * 16 + c];
                eval_one(xv, pa, acc[c]);
            }
        }

        // deterministic warp reduction, per-warp partial to fixed slot
        #pragma unroll
        for (int c = 0; c < 16; ++c) {
            float v = acc[c];
            v += __shfl_xor_sync(0xFFFFFFFFu, v, 16);
            v += __shfl_xor_sync(0xFFFFFFFFu, v, 8);
            v += __shfl_xor_sync(0xFFFFFFFFu, v, 4);
            v += __shfl_xor_sync(0xFFFFFFFFu, v, 2);
            v += __shfl_xor_sync(0xFFFFFFFFu, v, 1);
            if (lane == 0)
                g_partials[(size_t)warpG * NCAND + (g * 16 + c)] = v;
        }
    }
}

// ---------------- kernel 4: deterministic fp64 reduce per candidate ----------------
__global__ void k_reduce() {
    int c = blockIdx.x * blockDim.x + threadIdx.x;
    if (c >= NCAND) return;
    double s = 0.0;
    for (int w = 0; w < NWARPS; ++w)
        s += (double)g_partials[(size_t)w * NCAND + c];
    g_scores[c] = s;
}

// ---------------- kernel 5: lex-first argmin, emit [best_min, best_max] -----------
__global__ void k_argmin(float* __restrict__ out) {
    __shared__ double ssc[256];
    __shared__ int    sid[256];
    int t = threadIdx.x;
    double bs = 1e300;
    int bi = NCAND;
    for (int c = t; c < NCAND; c += 256) {
        double s = g_scores[c];
        if (s < bs) { bs = s; bi = c; }   // ascending c -> first-min kept
    }
    ssc[t] = bs; sid[t] = bi;
    __syncthreads();
    for (int off = 128; off > 0; off >>= 1) {
        if (t < off) {
            double so = ssc[t + off];
            int    io = sid[t + off];
            if (so < ssc[t] || (so == ssc[t] && io < sid[t])) {
                ssc[t] = so; sid[t] = io;
            }
        }
        __syncthreads();
    }
    if (t == 0) {
        int idx = sid[0];
        out[0] = g_bmin[idx];
        out[1] = g_bmax[idx];
    }
}

// ---------------- launch ----------------
extern "C" void kernel_launch(void* const* d_in, const int* in_sizes, int n_in,
                              void* d_out, int out_size) {
    const float* x = (const float*)d_in[0];
    float* out = (float*)d_out;
    int n = in_sizes[0];

    k_init<<<1, 1>>>();
    k_minmax<<<GRID, TPB>>>(x, n);
    k_candidates<<<(NCAND + TPB - 1) / TPB, TPB>>>();
    k_mse<<<GRID, TPB>>>(x, n);
    k_reduce<<<(NCAND + TPB - 1) / TPB, TPB>>>();
    k_argmin<<<1, 256>>>(out);
}

// round 2
// speedup vs baseline: 9.4752x; 9.4752x over previous
#include <cuda_runtime.h>
#include <cstdint>

// ---------------- constants ----------------
#define N_ELEM  4194304       // 1024 x 4096 (dataset fixed)
#define NCAND   1600          // 100 i-steps x 16 zero-points
#define TPB     256
#define GRID    296
#define NB      131072        // value bins (2^17)
#define NGRP    128           // NB / 1024 scan groups
#define EPS_F32 1.1920928955078125e-07f

// ---------------- device scratch ----------------
__device__ unsigned g_min_enc, g_max_enc;
__device__ float    g_sorted[N_ELEM];
__device__ unsigned g_hist[NB];
__device__ unsigned g_pwcnt[NB];
__device__ unsigned g_btot_cnt[NGRP];
__device__ unsigned g_boff_cnt[NGRP];
__device__ unsigned g_binstart[NB + 1];
__device__ unsigned g_binfill[NB];
__device__ double   g_pwsx[NB], g_pwsx2[NB];
__device__ double   g_btot_sx[NGRP], g_btot_sx2[NGRP];
__device__ double   g_boff_sx[NGRP], g_boff_sx2[NGRP];
__device__ double   g_tot_sx, g_tot_sx2;
__device__ float    g_scale[NCAND], g_zp[NCAND], g_bmin[NCAND], g_bmax[NCAND];
__device__ double   g_scores[NCAND];

// ---------------- helpers ----------------
__device__ __forceinline__ unsigned enc_f32(float f) {
    unsigned u = __float_as_uint(f);
    return (u & 0x80000000u) ? ~u : (u | 0x80000000u);
}
__device__ __forceinline__ float dec_f32(unsigned e) {
    unsigned u = (e & 0x80000000u) ? (e ^ 0x80000000u) : ~e;
    return __uint_as_float(u);
}
__device__ __forceinline__ void binparams(float& xmin, float& bs) {
    xmin = dec_f32(g_min_enc);
    float xmax = dec_f32(g_max_enc);
    bs = (float)NB / (xmax - xmin);
}
// monotone non-decreasing in v (sub + positive mul + trunc all monotone)
__device__ __forceinline__ int binof(float v, float xmin, float bs) {
    int j = (int)((v - xmin) * bs);
    j = j < 0 ? 0 : j;
    return j < NB ? j : (NB - 1);
}
__device__ __forceinline__ void kahan(float& s, float& c, float e) {
    float y = e - c;
    float t = s + y;
    c = (t - s) - y;
    s = t;
}

// ---------------- k0: init sentinels + zero histogram ----------------
__global__ void k_init_zero() {
    int tid = blockIdx.x * blockDim.x + threadIdx.x;
    if (tid < NB) g_hist[tid] = 0u;
    if (tid == 0) { g_min_enc = 0xFFFFFFFFu; g_max_enc = 0u; }
}

// ---------------- k1: global min/max ----------------
__global__ void k_minmax(const float* __restrict__ x, int n) {
    int tid = blockIdx.x * TPB + threadIdx.x;
    int stride = GRID * TPB;
    float lmin = 3.4e38f, lmax = -3.4e38f;
    int n4 = n >> 2;
    const float4* x4 = (const float4*)x;
    for (int p = tid; p < n4; p += stride) {
        float4 v = __ldg(x4 + p);
        lmin = fminf(lmin, fminf(fminf(v.x, v.y), fminf(v.z, v.w)));
        lmax = fmaxf(lmax, fmaxf(fmaxf(v.x, v.y), fmaxf(v.z, v.w)));
    }
    int r = n & 3;
    if (tid < r) {
        float v = x[n - r + tid];
        lmin = fminf(lmin, v);
        lmax = fmaxf(lmax, v);
    }
    unsigned emin = enc_f32(lmin), emax = enc_f32(lmax);
    emin = __reduce_min_sync(0xFFFFFFFFu, emin);
    emax = __reduce_max_sync(0xFFFFFFFFu, emax);
    if ((threadIdx.x & 31) == 0) {
        atomicMin(&g_min_enc, emin);
        atomicMax(&g_max_enc, emax);
    }
}

// ---------------- k2: candidate parameters (matches reference arithmetic) ---
__global__ void k_candidates() {
    int c = blockIdx.x * blockDim.x + threadIdx.x;
    if (c >= NCAND) return;
    float x_min = dec_f32(g_min_enc);
    float x_max = dec_f32(g_max_enc);
    float xrange = x_max - x_min;

    int i = c / 16 + 1;
    int j = c % 16;
    float fi = (float)i, zj = (float)j;

    float tmp_max   = __fmul_rn(__fdiv_rn(xrange, 100.0f), fi);
    float tmp_delta = __fdiv_rn(tmp_max, 15.0f);

    float zd = __fmul_rn(zj, tmp_delta);
    float new_min = fmaxf(-zd, x_min);
    float new_max = fminf(__fsub_rn(tmp_max, zd), x_max);
    float min_neg = fminf(new_min, 0.0f);
    float max_pos = fmaxf(new_max, 0.0f);
    float scale = fmaxf(__fdiv_rn(__fsub_rn(max_pos, min_neg), 15.0f), EPS_F32);
    float zp = fminf(fmaxf(0.0f - rintf(__fdiv_rn(min_neg, scale)), 0.0f), 15.0f);

    g_scale[c] = scale;
    g_zp[c]    = zp;
    g_bmin[c]  = new_min;
    g_bmax[c]  = new_max;
}

// ---------------- k3: histogram ----------------
__global__ void k_hist(const float* __restrict__ x, int n) {
    float xmin, bs; binparams(xmin, bs);
    int tid = blockIdx.x * TPB + threadIdx.x;
    int stride = GRID * TPB;
    int n4 = n >> 2;
    const float4* x4 = (const float4*)x;
    for (int p = tid; p < n4; p += stride) {
        float4 v = __ldg(x4 + p);
        atomicAdd(&g_hist[binof(v.x, xmin, bs)], 1u);
        atomicAdd(&g_hist[binof(v.y, xmin, bs)], 1u);
        atomicAdd(&g_hist[binof(v.z, xmin, bs)], 1u);
        atomicAdd(&g_hist[binof(v.w, xmin, bs)], 1u);
    }
    int r = n & 3;
    if (tid < r) atomicAdd(&g_hist[binof(x[n - r + tid], xmin, bs)], 1u);
}

// ---------------- k4: per-group exclusive scan of counts ----------------
__global__ void __launch_bounds__(1024) k_scan_cnt_A() {
    __shared__ unsigned sh[1024];
    int t = threadIdx.x;
    int j = blockIdx.x * 1024 + t;
    unsigned v = g_hist[j];
    sh[t] = v;
    __syncthreads();
    for (int off = 1; off < 1024; off <<= 1) {
        unsigned a = (t >= off) ? sh[t - off] : 0u;
        __syncthreads();
        sh[t] += a;
        __syncthreads();
    }
    g_pwcnt[j] = (t == 0) ? 0u : sh[t - 1];
    if (t == 1023) g_btot_cnt[blockIdx.x] = sh[1023];
}

// ---------------- k5: scan of 128 group totals ----------------
__global__ void k_scan_cnt_B() {
    __shared__ unsigned sh[NGRP];
    int t = threadIdx.x;
    sh[t] = g_btot_cnt[t];
    __syncthreads();
    for (int off = 1; off < NGRP; off <<= 1) {
        unsigned a = (t >= off) ? sh[t - off] : 0u;
        __syncthreads();
        sh[t] += a;
        __syncthreads();
    }
    g_boff_cnt[t] = (t == 0) ? 0u : sh[t - 1];
}

// ---------------- k6: materialize binstart + fill cursors ----------------
__global__ void k_fill(int n) {
    int j = blockIdx.x * blockDim.x + threadIdx.x;
    if (j < NB) {
        unsigned s = g_pwcnt[j] + g_boff_cnt[j >> 10];
        g_binstart[j] = s;
        g_binfill[j]  = s;
    }
    if (j == 0) g_binstart[NB] = (unsigned)n;
}

// ---------------- k7: scatter (counting sort) ----------------
__global__ void k_scatter(const float* __restrict__ x, int n) {
    float xmin, bs; binparams(xmin, bs);
    int tid = blockIdx.x * TPB + threadIdx.x;
    int stride = GRID * TPB;
    int n4 = n >> 2;
    const float4* x4 = (const float4*)x;
    for (int p = tid; p < n4; p += stride) {
        float4 v = __ldg(x4 + p);
        unsigned p0 = atomicAdd(&g_binfill[binof(v.x, xmin, bs)], 1u); g_sorted[p0] = v.x;
        unsigned p1 = atomicAdd(&g_binfill[binof(v.y, xmin, bs)], 1u); g_sorted[p1] = v.y;
        unsigned p2 = atomicAdd(&g_binfill[binof(v.z, xmin, bs)], 1u); g_sorted[p2] = v.z;
        unsigned p3 = atomicAdd(&g_binfill[binof(v.w, xmin, bs)], 1u); g_sorted[p3] = v.w;
    }
    int r = n & 3;
    if (tid < r) {
        float v = x[n - r + tid];
        unsigned p0 = atomicAdd(&g_binfill[binof(v, xmin, bs)], 1u);
        g_sorted[p0] = v;
    }
}

// ---------------- k8: per-bin Kahan sums + per-group fp64 exclusive scan ----
__global__ void __launch_bounds__(1024) k_aggr_scan() {
    __shared__ double shd[1024];
    int t = threadIdx.x;
    int j = blockIdx.x * 1024 + t;
    unsigned s0 = g_binstart[j], s1 = g_binstart[j + 1];
    float s = 0.f, c = 0.f, s2 = 0.f, c2 = 0.f;
    for (unsigned u = s0; u < s1; ++u) {
        float e = g_sorted[u];
        kahan(s, c, e);
        kahan(s2, c2, e * e);
    }
    double dx  = (double)s  - (double)c;
    double dx2 = (double)s2 - (double)c2;

    // scan Σx
    shd[t] = dx;
    __syncthreads();
    for (int off = 1; off < 1024; off <<= 1) {
        double a = (t >= off) ? shd[t - off] : 0.0;
        __syncthreads();
        shd[t] += a;
        __syncthreads();
    }
    g_pwsx[j] = (t == 0) ? 0.0 : shd[t - 1];
    if (t == 1023) g_btot_sx[blockIdx.x] = shd[1023];
    __syncthreads();

    // scan Σx²
    shd[t] = dx2;
    __syncthreads();
    for (int off = 1; off < 1024; off <<= 1) {
        double a = (t >= off) ? shd[t - off] : 0.0;
        __syncthreads();
        shd[t] += a;
        __syncthreads();
    }
    g_pwsx2[j] = (t == 0) ? 0.0 : shd[t - 1];
    if (t == 1023) g_btot_sx2[blockIdx.x] = shd[1023];
}

// ---------------- k9: scan group totals (fp64 x2) ----------------
__global__ void k_scan_sum_B() {
    __shared__ double sh[NGRP];
    int t = threadIdx.x;

    sh[t] = g_btot_sx[t];
    __syncthreads();
    for (int off = 1; off < NGRP; off <<= 1) {
        double a = (t >= off) ? sh[t - off] : 0.0;
        __syncthreads();
        sh[t] += a;
        __syncthreads();
    }
    g_boff_sx[t] = (t == 0) ? 0.0 : sh[t - 1];
    if (t == NGRP - 1) g_tot_sx = sh[NGRP - 1];
    __syncthreads();

    sh[t] = g_btot_sx2[t];
    __syncthreads();
    for (int off = 1; off < NGRP; off <<= 1) {
        double a = (t >= off) ? sh[t - off] : 0.0;
        __syncthreads();
        sh[t] += a;
        __syncthreads();
    }
    g_boff_sx2[t] = (t == 0) ? 0.0 : sh[t - 1];
    if (t == NGRP - 1) g_tot_sx2 = sh[NGRP - 1];
}

// ---------------- k10: evaluate all candidates (1 warp each) ----------------
__global__ void __launch_bounds__(256) k_eval(int n) {
    int cand = blockIdx.x * 8 + (threadIdx.x >> 5);
    int lane = threadIdx.x & 31;
    if (cand >= NCAND) return;

    float s = g_scale[cand], z = g_zp[cand];
    float xmin, bs; binparams(xmin, bs);

    // F_k = (count, Σx, Σx²) of elements strictly below boundary B_k.
    // lane 0 -> F_0 = 0 ; lanes 1..15 -> boundaries ; lane 16 -> totals.
    double dcnt = 0.0, dsx = 0.0, dsx2 = 0.0;
    if (lane >= 1 && lane <= 15) {
        double bd = (double)s * ((double)lane - (double)z - 0.5);
        float bf = (float)bd;
        float tt = (bf - xmin) * bs;
        int j = (int)floorf(tt);
        j = j < 0 ? 0 : (j >= NB ? NB - 1 : j);
        unsigned s0 = g_binstart[j], s1 = g_binstart[j + 1];
        dcnt = (double)g_binstart[j];
        dsx  = g_pwsx[j]  + g_boff_sx[j >> 10];
        dsx2 = g_pwsx2[j] + g_boff_sx2[j >> 10];
        int   pcnt = 0;
        float ps = 0.f, pc = 0.f, ps2 = 0.f, pc2 = 0.f;
        for (unsigned u = s0; u < s1; ++u) {
            float e = g_sorted[u];
            if (e < bf) {
                pcnt++;
                kahan(ps, pc, e);
                kahan(ps2, pc2, e * e);
            }
        }
        dcnt += (double)pcnt;
        dsx  += (double)ps  - (double)pc;
        dsx2 += (double)ps2 - (double)pc2;
    } else if (lane == 16) {
        dcnt = (double)n;
        dsx  = g_tot_sx;
        dsx2 = g_tot_sx2;
    }
    __syncwarp();

    double ncnt = __shfl_down_sync(0xFFFFFFFFu, dcnt, 1);
    double nsx  = __shfl_down_sync(0xFFFFFFFFu, dsx, 1);
    double nsx2 = __shfl_down_sync(0xFFFFFFFFu, dsx2, 1);

    double term = 0.0;
    if (lane < 16) {
        float v = ((float)lane - z) * s;   // matches fl((k - z) * s)
        double vd = (double)v;
        double segc  = ncnt - dcnt;
        double segx  = nsx  - dsx;
        double segx2 = nsx2 - dsx2;
        term = segx2 - 2.0 * vd * segx + vd * vd * segc;
    }
    #pragma unroll
    for (int off = 16; off > 0; off >>= 1)
        term += __shfl_xor_sync(0xFFFFFFFFu, term, off);
    if (lane == 0) g_scores[cand] = term;
}

// ---------------- k11: lex-first argmin, emit [best_min, best_max] ---------
__global__ void k_argmin(float* __restrict__ out) {
    __shared__ double ssc[256];
    __shared__ int    sid[256];
    int t = threadIdx.x;
    double bsd = 1e300;
    int bi = NCAND;
    for (int c = t; c < NCAND; c += 256) {
        double sv = g_scores[c];
        if (sv < bsd) { bsd = sv; bi = c; }
    }
    ssc[t] = bsd; sid[t] = bi;
    __syncthreads();
    for (int off = 128; off > 0; off >>= 1) {
        if (t < off) {
            double so = ssc[t + off];
            int    io = sid[t + off];
            if (so < ssc[t] || (so == ssc[t] && io < sid[t])) {
                ssc[t] = so; sid[t] = io;
            }
        }
        __syncthreads();
    }
    if (t == 0) {
        int idx = sid[0];
        out[0] = g_bmin[idx];
        out[1] = g_bmax[idx];
    }
}

// ---------------- launch ----------------
extern "C" void kernel_launch(void* const* d_in, const int* in_sizes, int n_in,
                              void* d_out, int out_size) {
    const float* x = (const float*)d_in[0];
    float* out = (float*)d_out;
    int n = in_sizes[0];

    k_init_zero<<<(NB + TPB - 1) / TPB, TPB>>>();
    k_minmax<<<GRID, TPB>>>(x, n);
    k_candidates<<<(NCAND + TPB - 1) / TPB, TPB>>>();
    k_hist<<<GRID, TPB>>>(x, n);
    k_scan_cnt_A<<<NGRP, 1024>>>();
    k_scan_cnt_B<<<1, NGRP>>>();
    k_fill<<<(NB + TPB - 1) / TPB, TPB>>>(n);
    k_scatter<<<GRID, TPB>>>(x, n);
    k_aggr_scan<<<NGRP, 1024>>>();
    k_scan_sum_B<<<1, NGRP>>>();
    k_eval<<<NCAND / 8, 256>>>(n);
    k_argmin<<<1, 256>>>(out);
}

// round 3
// speedup vs baseline: 11.7074x; 1.2356x over previous
#include <cuda_runtime.h>
#include <cstdint>

// ---------------- constants ----------------
#define N_ELEM  4194304
#define NCAND   1600          // 100 i-steps x 16 zero-points
#define NBND    (NCAND * 15)  // 24000 boundaries
#define TPB     256
#define GRID    296
#define NB      131072        // fine value bins (2^17)
#define NGRP    128           // NB / 1024
#define EPS_F32 1.1920928955078125e-07f
#define FXS     1099511627776.0f   // 2^40
#define FXSI    (1.0 / 1099511627776.0)
#define PMASK   0x0000FFFFFFFFFFFFULL

// ---------------- device scratch ----------------
__device__ unsigned g_min_enc, g_max_enc;
// candidates
__device__ float    g_scale[NCAND], g_zp[NCAND], g_bmin[NCAND], g_bmax[NCAND];
// boundaries
__device__ float    g_bndval[NBND];
__device__ int      g_bndbin[NBND];
__device__ unsigned long long g_part[NBND];
__device__ unsigned g_bndcnt[NB];
__device__ unsigned g_pwb[NB];
__device__ unsigned g_gtb[NGRP], g_gob[NGRP];
__device__ unsigned g_bndoff[NB];      // CSR start
__device__ unsigned g_bndcur[NB];      // scatter cursor
__device__ float    g_listval[NBND];
__device__ int      g_listid[NBND];
__device__ unsigned g_bitmap[NB / 32];
// per-bin accumulators + scans
__device__ unsigned long long g_acc[NB];
__device__ unsigned g_pwcnt[NB];
__device__ unsigned g_btot_cnt[NGRP], g_boff_cnt[NGRP];
__device__ double   g_pwsx[NB];
__device__ double   g_btot_sx[NGRP], g_boff_sx[NGRP];
__device__ double   g_tot_sx;
// scores
__device__ double   g_scores[NCAND];

// ---------------- helpers ----------------
__device__ __forceinline__ unsigned enc_f32(float f) {
    unsigned u = __float_as_uint(f);
    return (u & 0x80000000u) ? ~u : (u | 0x80000000u);
}
__device__ __forceinline__ float dec_f32(unsigned e) {
    unsigned u = (e & 0x80000000u) ? (e ^ 0x80000000u) : ~e;
    return __uint_as_float(u);
}
__device__ __forceinline__ void binparams(float& xmin, float& bs, float& binw) {
    xmin = dec_f32(g_min_enc);
    float xmax = dec_f32(g_max_enc);
    float range = xmax - xmin;
    bs   = (float)NB / range;
    binw = range / (float)NB;
}
// monotone non-decreasing in v
__device__ __forceinline__ int binof(float v, float xmin, float bs) {
    int j = (int)((v - xmin) * bs);
    j = j < 0 ? 0 : j;
    return j < NB ? j : (NB - 1);
}
__device__ __forceinline__ float binlo_f(int j, float xmin, float binw) {
    return __fmaf_rn((float)j, binw, xmin);   // must match everywhere
}
__device__ __forceinline__ unsigned long long packv(float v, int j, float xmin, float binw) {
    float offs = v - binlo_f(j, xmin, binw);
    offs = fmaxf(offs, 0.0f);
    return (1ULL << 48) | (unsigned long long)(offs * FXS);
}

// ---------------- k0: zero everything ----------------
__global__ void k_init() {
    int tid = blockIdx.x * blockDim.x + threadIdx.x;
    int stride = gridDim.x * blockDim.x;
    for (int i = tid; i < NB; i += stride) {
        g_acc[i] = 0ULL;
        g_bndcnt[i] = 0u;
    }
    for (int i = tid; i < NB / 32; i += stride) g_bitmap[i] = 0u;
    for (int i = tid; i < NBND; i += stride) g_part[i] = 0ULL;
    if (tid == 0) { g_min_enc = 0xFFFFFFFFu; g_max_enc = 0u; }
}

// ---------------- k1: global min/max ----------------
__global__ void k_minmax(const float* __restrict__ x, int n) {
    int tid = blockIdx.x * TPB + threadIdx.x;
    int stride = GRID * TPB;
    float lmin = 3.4e38f, lmax = -3.4e38f;
    int n4 = n >> 2;
    const float4* x4 = (const float4*)x;
    for (int p = tid; p < n4; p += stride) {
        float4 v = __ldg(x4 + p);
        lmin = fminf(lmin, fminf(fminf(v.x, v.y), fminf(v.z, v.w)));
        lmax = fmaxf(lmax, fmaxf(fmaxf(v.x, v.y), fmaxf(v.z, v.w)));
    }
    int r = n & 3;
    if (tid < r) {
        float v = x[n - r + tid];
        lmin = fminf(lmin, v);
        lmax = fmaxf(lmax, v);
    }
    unsigned emin = enc_f32(lmin), emax = enc_f32(lmax);
    emin = __reduce_min_sync(0xFFFFFFFFu, emin);
    emax = __reduce_max_sync(0xFFFFFFFFu, emax);
    if ((threadIdx.x & 31) == 0) {
        atomicMin(&g_min_enc, emin);
        atomicMax(&g_max_enc, emax);
    }
}

// ---------------- k2: candidate parameters ----------------
__global__ void k_candidates() {
    int c = blockIdx.x * blockDim.x + threadIdx.x;
    if (c >= NCAND) return;
    float x_min = dec_f32(g_min_enc);
    float x_max = dec_f32(g_max_enc);
    float xrange = x_max - x_min;

    int i = c / 16 + 1;
    int j = c % 16;
    float fi = (float)i, zj = (float)j;

    float tmp_max   = __fmul_rn(__fdiv_rn(xrange, 100.0f), fi);
    float tmp_delta = __fdiv_rn(tmp_max, 15.0f);

    float zd = __fmul_rn(zj, tmp_delta);
    float new_min = fmaxf(-zd, x_min);
    float new_max = fminf(__fsub_rn(tmp_max, zd), x_max);
    float min_neg = fminf(new_min, 0.0f);
    float max_pos = fmaxf(new_max, 0.0f);
    float scale = fmaxf(__fdiv_rn(__fsub_rn(max_pos, min_neg), 15.0f), EPS_F32);
    float zp = fminf(fmaxf(0.0f - rintf(__fdiv_rn(min_neg, scale)), 0.0f), 15.0f);

    g_scale[c] = scale;
    g_zp[c]    = zp;
    g_bmin[c]  = new_min;
    g_bmax[c]  = new_max;
}

// ---------------- k3: boundaries -> bins, counts, bitmap ----------------
__global__ void k_bnd() {
    int id = blockIdx.x * blockDim.x + threadIdx.x;
    if (id >= NBND) return;
    int c = id / 15;
    int k = id % 15 + 1;      // 1..15
    float s = g_scale[c], z = g_zp[c];
    double bd = (double)s * ((double)k - (double)z - 0.5);
    float bf = (float)bd;
    float xmin, bs, binw; binparams(xmin, bs, binw);
    int j = binof(bf, xmin, bs);
    g_bndval[id] = bf;
    g_bndbin[id] = j;
    atomicAdd(&g_bndcnt[j], 1u);
    atomicOr(&g_bitmap[j >> 5], 1u << (j & 31));
}

// ---------------- k4/k5: scan boundary counts (CSR offsets) ----------------
__global__ void __launch_bounds__(1024) k_scanb_A() {
    __shared__ unsigned sh[1024];
    int t = threadIdx.x;
    int j = blockIdx.x * 1024 + t;
    sh[t] = g_bndcnt[j];
    __syncthreads();
    for (int off = 1; off < 1024; off <<= 1) {
        unsigned a = (t >= off) ? sh[t - off] : 0u;
        __syncthreads();
        sh[t] += a;
        __syncthreads();
    }
    g_pwb[j] = (t == 0) ? 0u : sh[t - 1];
    if (t == 1023) g_gtb[blockIdx.x] = sh[1023];
}
__global__ void k_scanb_B() {
    __shared__ unsigned sh[NGRP];
    int t = threadIdx.x;
    sh[t] = g_gtb[t];
    __syncthreads();
    for (int off = 1; off < NGRP; off <<= 1) {
        unsigned a = (t >= off) ? sh[t - off] : 0u;
        __syncthreads();
        sh[t] += a;
        __syncthreads();
    }
    g_gob[t] = (t == 0) ? 0u : sh[t - 1];
}
__global__ void k_bndfill() {
    int j = blockIdx.x * blockDim.x + threadIdx.x;
    if (j >= NB) return;
    unsigned s = g_pwb[j] + g_gob[j >> 10];
    g_bndoff[j] = s;
    g_bndcur[j] = s;
}
__global__ void k_bndscatter() {
    int id = blockIdx.x * blockDim.x + threadIdx.x;
    if (id >= NBND) return;
    int j = g_bndbin[id];
    unsigned pos = atomicAdd(&g_bndcur[j], 1u);
    g_listval[pos] = g_bndval[id];
    g_listid[pos]  = id;
}

// ---------------- k6: THE single heavy pass ----------------
__device__ __forceinline__ void main_one(float v, float xmin, float bs, float binw,
                                         const unsigned* __restrict__ bm) {
    int j = binof(v, xmin, bs);
    unsigned long long pk = packv(v, j, xmin, binw);
    atomicAdd(&g_acc[j], pk);
    if ((bm[j >> 5] >> (j & 31)) & 1u) {
        unsigned b0 = g_bndoff[j];
        unsigned b1 = b0 + g_bndcnt[j];
        for (unsigned b = b0; b < b1; ++b) {
            if (v < g_listval[b])
                atomicAdd(&g_part[g_listid[b]], pk);
        }
    }
}

__global__ void __launch_bounds__(TPB) k_main(const float* __restrict__ x, int n) {
    __shared__ unsigned bm[NB / 32];
    for (int i = threadIdx.x; i < NB / 32; i += TPB) bm[i] = g_bitmap[i];
    __syncthreads();
    float xmin, bs, binw; binparams(xmin, bs, binw);

    int tid = blockIdx.x * TPB + threadIdx.x;
    int stride = GRID * TPB;
    int n4 = n >> 2;
    const float4* x4 = (const float4*)x;
    for (int p = tid; p < n4; p += stride) {
        float4 v = __ldg(x4 + p);
        main_one(v.x, xmin, bs, binw, bm);
        main_one(v.y, xmin, bs, binw, bm);
        main_one(v.z, xmin, bs, binw, bm);
        main_one(v.w, xmin, bs, binw, bm);
    }
    int r = n & 3;
    if (tid < r) main_one(x[n - r + tid], xmin, bs, binw, bm);
}

// ---------------- k7/k8: per-bin decode + exclusive scans ----------------
__global__ void __launch_bounds__(1024) k_accscan_A() {
    __shared__ unsigned shc[1024];
    __shared__ double   shd[1024];
    int t = threadIdx.x;
    int j = blockIdx.x * 1024 + t;
    float xmin, bs, binw; binparams(xmin, bs, binw);

    unsigned long long a = g_acc[j];
    unsigned cnt = (unsigned)(a >> 48);
    double offsum = (double)(a & PMASK) * FXSI;
    double dx = (double)cnt * (double)binlo_f(j, xmin, binw) + offsum;

    shc[t] = cnt;
    __syncthreads();
    for (int off = 1; off < 1024; off <<= 1) {
        unsigned v = (t >= off) ? shc[t - off] : 0u;
        __syncthreads();
        shc[t] += v;
        __syncthreads();
    }
    g_pwcnt[j] = (t == 0) ? 0u : shc[t - 1];
    if (t == 1023) g_btot_cnt[blockIdx.x] = shc[1023];
    __syncthreads();

    shd[t] = dx;
    __syncthreads();
    for (int off = 1; off < 1024; off <<= 1) {
        double v = (t >= off) ? shd[t - off] : 0.0;
        __syncthreads();
        shd[t] += v;
        __syncthreads();
    }
    g_pwsx[j] = (t == 0) ? 0.0 : shd[t - 1];
    if (t == 1023) g_btot_sx[blockIdx.x] = shd[1023];
}
__global__ void k_accscan_B() {
    __shared__ unsigned shc[NGRP];
    __shared__ double   shd[NGRP];
    int t = threadIdx.x;
    shc[t] = g_btot_cnt[t];
    shd[t] = g_btot_sx[t];
    __syncthreads();
    for (int off = 1; off < NGRP; off <<= 1) {
        unsigned vc = (t >= off) ? shc[t - off] : 0u;
        double   vd = (t >= off) ? shd[t - off] : 0.0;
        __syncthreads();
        shc[t] += vc;
        shd[t] += vd;
        __syncthreads();
    }
    g_boff_cnt[t] = (t == 0) ? 0u : shc[t - 1];
    g_boff_sx[t]  = (t == 0) ? 0.0 : shd[t - 1];
    if (t == NGRP - 1) g_tot_sx = shd[NGRP - 1];
}

// ---------------- k9: evaluate candidates (warp each, pure lookup) ---------
__global__ void __launch_bounds__(256) k_eval(int n) {
    int cand = blockIdx.x * 8 + (threadIdx.x >> 5);
    int lane = threadIdx.x & 31;
    if (cand >= NCAND) return;

    float s = g_scale[cand], z = g_zp[cand];
    float xmin, bs, binw; binparams(xmin, bs, binw);

    double dcnt = 0.0, dsx = 0.0;
    if (lane >= 1 && lane <= 15) {
        int id = cand * 15 + (lane - 1);
        int j = g_bndbin[id];
        unsigned long long pp = g_part[id];
        unsigned pcnt = (unsigned)(pp >> 48);
        double poff = (double)(pp & PMASK) * FXSI;
        dcnt = (double)(g_pwcnt[j] + g_boff_cnt[j >> 10]) + (double)pcnt;
        dsx  = g_pwsx[j] + g_boff_sx[j >> 10]
             + (double)pcnt * (double)binlo_f(j, xmin, binw) + poff;
    } else if (lane == 16) {
        dcnt = (double)n;
        dsx  = g_tot_sx;
    }
    __syncwarp();

    double ncnt = __shfl_down_sync(0xFFFFFFFFu, dcnt, 1);
    double nsx  = __shfl_down_sync(0xFFFFFFFFu, dsx, 1);

    double term = 0.0;
    if (lane < 16) {
        float v = ((float)lane - z) * s;
        double vd = (double)v;
        double segc = ncnt - dcnt;
        double segx = nsx  - dsx;
        term = vd * vd * segc - 2.0 * vd * segx;   // Sum(x^2) dropped: constant across candidates
    }
    #pragma unroll
    for (int off = 16; off > 0; off >>= 1)
        term += __shfl_xor_sync(0xFFFFFFFFu, term, off);
    if (lane == 0) g_scores[cand] = term;
}

// ---------------- k10: lex-first argmin ----------------
__global__ void k_argmin(float* __restrict__ out) {
    __shared__ double ssc[256];
    __shared__ int    sid[256];
    int t = threadIdx.x;
    double bsd = 1e300;
    int bi = NCAND;
    for (int c = t; c < NCAND; c += 256) {
        double sv = g_scores[c];
        if (sv < bsd) { bsd = sv; bi = c; }
    }
    ssc[t] = bsd; sid[t] = bi;
    __syncthreads();
    for (int off = 128; off > 0; off >>= 1) {
        if (t < off) {
            double so = ssc[t + off];
            int    io = sid[t + off];
            if (so < ssc[t] || (so == ssc[t] && io < sid[t])) {
                ssc[t] = so; sid[t] = io;
            }
        }
        __syncthreads();
    }
    if (t == 0) {
        int idx = sid[0];
        out[0] = g_bmin[idx];
        out[1] = g_bmax[idx];
    }
}

// ---------------- launch ----------------
extern "C" void kernel_launch(void* const* d_in, const int* in_sizes, int n_in,
                              void* d_out, int out_size) {
    const float* x = (const float*)d_in[0];
    float* out = (float*)d_out;
    int n = in_sizes[0];

    k_init<<<GRID, TPB>>>();
    k_minmax<<<GRID, TPB>>>(x, n);
    k_candidates<<<(NCAND + TPB - 1) / TPB, TPB>>>();
    k_bnd<<<(NBND + TPB - 1) / TPB, TPB>>>();
    k_scanb_A<<<NGRP, 1024>>>();
    k_scanb_B<<<1, NGRP>>>();
    k_bndfill<<<(NB + TPB - 1) / TPB, TPB>>>();
    k_bndscatter<<<(NBND + TPB - 1) / TPB, TPB>>>();
    k_main<<<GRID, TPB>>>(x, n);
    k_accscan_A<<<NGRP, 1024>>>();
    k_accscan_B<<<1, NGRP>>>();
    k_eval<<<NCAND / 8, 256>>>(n);
    k_argmin<<<1, 256>>>(out);
}

// round 8
// speedup vs baseline: 16.4596x; 1.4059x over previous
#include <cuda_runtime.h>
#include <cstdint>

// ---------------- constants ----------------
#define NCAND   1600
#define NBND    (NCAND * 15)        // 24000
#define NB      131072              // fine value bins
#define TPB     256
#define GRID1   592                 // k1 blocks
#define K2G     128                 // k2 blocks (resident -> grid barrier safe)
#define GRID3   888                 // k3 blocks (6/SM)
#define K4G     128                 // k4 blocks
#define EPS_F32 1.1920928955078125e-07f
#define FXS     1099511627776.0f    // 2^40
#define FXSI    (1.0 / 1099511627776.0)
#define PMASK   0x0000FFFFFFFFFFFFULL

// ---------------- device state ----------------
__device__ unsigned g_bminenc[GRID1], g_bmaxenc[GRID1];
__device__ float    g_xminF, g_xmaxF, g_bsF, g_binwF;
__device__ float    g_scale[NCAND], g_zp[NCAND], g_cmin[NCAND], g_cmax[NCAND];
__device__ float    g_bndval[NBND];
__device__ int      g_bndbin[NBND];
__device__ unsigned g_bndcnt[NB];
__device__ unsigned g_bndmeta[NB];      // (csr_off << 16) | cnt
__device__ unsigned g_bndcur[NB];
__device__ uint2    g_list[NBND];       // {valbits, id}
__device__ unsigned g_bitmap[NB / 32];
__device__ unsigned long long g_acc[NB];
__device__ unsigned long long g_part[NBND];
__device__ unsigned g_pwcnt[NB];
__device__ double   g_pwsx[NB];
__device__ unsigned g_psum2[K2G];
__device__ unsigned g_ptotc[K4G];
__device__ double   g_ptotx[K4G];
__device__ double   g_totsx;
__device__ double   g_scores[NCAND];
__device__ unsigned g_bars[8];

// ---------------- helpers ----------------
__device__ __forceinline__ unsigned enc_f32(float f) {
    unsigned u = __float_as_uint(f);
    return (u & 0x80000000u) ? ~u : (u | 0x80000000u);
}
__device__ __forceinline__ float dec_f32(unsigned e) {
    unsigned u = (e & 0x80000000u) ? (e ^ 0x80000000u) : ~e;
    return __uint_as_float(u);
}
__device__ __forceinline__ int binof(float v, float xmin, float bs) {
    int j = (int)((v - xmin) * bs);
    j = j < 0 ? 0 : j;
    return j < NB ? j : (NB - 1);
}
__device__ __forceinline__ float binlo(int j, float xmin, float binw) {
    return __fmaf_rn((float)j, binw, xmin);
}
// software grid barrier — requires all gridDim blocks resident
__device__ __forceinline__ void gbar(unsigned* ctr, unsigned target) {
    __threadfence();
    __syncthreads();
    if (threadIdx.x == 0) {
        atomicAdd(ctr, 1u);
        while (*((volatile unsigned*)ctr) < target) {}
    }
    __syncthreads();
}
__device__ __forceinline__ void cand_params(int c, float x_min, float x_max,
                                            float& scale, float& zp,
                                            float& nmin, float& nmax) {
    float xrange = x_max - x_min;
    int i = c / 16 + 1;
    int j = c % 16;
    float fi = (float)i, zj = (float)j;
    float tmp_max   = __fmul_rn(__fdiv_rn(xrange, 100.0f), fi);
    float tmp_delta = __fdiv_rn(tmp_max, 15.0f);
    float zd = __fmul_rn(zj, tmp_delta);
    nmin = fmaxf(-zd, x_min);
    nmax = fminf(__fsub_rn(tmp_max, zd), x_max);
    float min_neg = fminf(nmin, 0.0f);
    float max_pos = fmaxf(nmax, 0.0f);
    scale = fmaxf(__fdiv_rn(__fsub_rn(max_pos, min_neg), 15.0f), EPS_F32);
    zp = fminf(fmaxf(0.0f - rintf(__fdiv_rn(min_neg, scale)), 0.0f), 15.0f);
}

// ================= k1: zero state + global min/max =================
__global__ void __launch_bounds__(TPB) k1_zero_minmax(const float* __restrict__ x, int n) {
    int tid = blockIdx.x * TPB + threadIdx.x;
    int stride = GRID1 * TPB;
    for (int i = tid; i < NB; i += stride) { g_acc[i] = 0ULL; g_bndcnt[i] = 0u; }
    for (int i = tid; i < NB / 32; i += stride) g_bitmap[i] = 0u;
    for (int i = tid; i < NBND; i += stride) g_part[i] = 0ULL;
    if (tid < 8) g_bars[tid] = 0u;

    float lmin = 3.4e38f, lmax = -3.4e38f;
    int n4 = n >> 2;
    const float4* x4 = (const float4*)x;
    for (int p = tid; p < n4; p += stride) {
        float4 v = __ldg(x4 + p);
        lmin = fminf(lmin, fminf(fminf(v.x, v.y), fminf(v.z, v.w)));
        lmax = fmaxf(lmax, fmaxf(fmaxf(v.x, v.y), fmaxf(v.z, v.w)));
    }
    int r = n & 3;
    if (tid < r) {
        float v = x[n - r + tid];
        lmin = fminf(lmin, v);
        lmax = fmaxf(lmax, v);
    }
    unsigned emin = __reduce_min_sync(0xFFFFFFFFu, enc_f32(lmin));
    unsigned emax = __reduce_max_sync(0xFFFFFFFFu, enc_f32(lmax));
    __shared__ unsigned smn[TPB / 32], smx[TPB / 32];
    int wid = threadIdx.x >> 5, lane = threadIdx.x & 31;
    if (lane == 0) { smn[wid] = emin; smx[wid] = emax; }
    __syncthreads();
    if (wid == 0) {
        unsigned a = (lane < TPB / 32) ? smn[lane] : 0xFFFFFFFFu;
        unsigned b = (lane < TPB / 32) ? smx[lane] : 0u;
        a = __reduce_min_sync(0xFFFFFFFFu, a);
        b = __reduce_max_sync(0xFFFFFFFFu, b);
        if (lane == 0) { g_bminenc[blockIdx.x] = a; g_bmaxenc[blockIdx.x] = b; }
    }
}

// ================= k2: minmax-reduce + candidates + boundary CSR ============
__global__ void __launch_bounds__(256) k2_bnd() {
    int t = threadIdx.x, b = blockIdx.x;
    int gid = b * 256 + t;

    // phase 0: block 0 reduces per-block minmax partials
    if (b == 0) {
        unsigned emin = 0xFFFFFFFFu, emax = 0u;
        for (int i = t; i < GRID1; i += 256) {
            emin = min(emin, g_bminenc[i]);
            emax = max(emax, g_bmaxenc[i]);
        }
        emin = __reduce_min_sync(0xFFFFFFFFu, emin);
        emax = __reduce_max_sync(0xFFFFFFFFu, emax);
        __shared__ unsigned smn[8], smx[8];
        int wid = t >> 5, lane = t & 31;
        if (lane == 0) { smn[wid] = emin; smx[wid] = emax; }
        __syncthreads();
        if (wid == 0) {
            unsigned a = (lane < 8) ? smn[lane] : 0xFFFFFFFFu;
            unsigned c = (lane < 8) ? smx[lane] : 0u;
            a = __reduce_min_sync(0xFFFFFFFFu, a);
            c = __reduce_max_sync(0xFFFFFFFFu, c);
            if (lane == 0) {
                float xmin = dec_f32(a), xmax = dec_f32(c);
                g_xminF = xmin; g_xmaxF = xmax;
                float range = xmax - xmin;
                g_bsF = (float)NB / range;
                g_binwF = range / (float)NB;
            }
        }
    }
    gbar(&g_bars[0], K2G);

    float xmin = g_xminF, xmax = g_xmaxF, bs = g_bsF;

    // phase 1: candidates + boundaries
    if (gid < NCAND) {
        float s, z, nm, nx;
        cand_params(gid, xmin, xmax, s, z, nm, nx);
        g_scale[gid] = s; g_zp[gid] = z; g_cmin[gid] = nm; g_cmax[gid] = nx;
    }
    if (gid < NBND) {
        int c = gid / 15, k = gid % 15 + 1;
        float s, z, nm, nx;
        cand_params(c, xmin, xmax, s, z, nm, nx);
        double bd = (double)s * ((double)k - (double)z - 0.5);
        float bf = (float)bd;
        int j = binof(bf, xmin, bs);
        g_bndval[gid] = bf;
        g_bndbin[gid] = j;
        atomicAdd(&g_bndcnt[j], 1u);
        atomicOr(&g_bitmap[j >> 5], 1u << (j & 31));
    }
    gbar(&g_bars[1], K2G);

    // phase 2a: per-partition scan (1024 bins / block, 4 per thread)
    int base = b * 1024;
    uint4 cc = *(const uint4*)&g_bndcnt[base + t * 4];
    unsigned ts = cc.x + cc.y + cc.z + cc.w;
    __shared__ unsigned sh[256];
    sh[t] = ts;
    __syncthreads();
    for (int off = 1; off < 256; off <<= 1) {
        unsigned v = (t >= off) ? sh[t - off] : 0u;
        __syncthreads();
        sh[t] += v;
        __syncthreads();
    }
    unsigned excl = sh[t] - ts;
    unsigned o0 = excl, o1 = o0 + cc.x, o2 = o1 + cc.y, o3 = o2 + cc.z;
    if (t == 255) g_psum2[b] = sh[255];
    gbar(&g_bars[2], K2G);

    // phase 2b: block offset + write meta/cursors
    __shared__ unsigned shoff;
    if (t == 0) {
        unsigned o = 0;
        for (int q = 0; q < b; ++q) o += __ldcg(&g_psum2[q]);
        shoff = o;
    }
    __syncthreads();
    unsigned off = shoff;
    g_bndmeta[base + t * 4 + 0] = ((o0 + off) << 16) | cc.x;
    g_bndmeta[base + t * 4 + 1] = ((o1 + off) << 16) | cc.y;
    g_bndmeta[base + t * 4 + 2] = ((o2 + off) << 16) | cc.z;
    g_bndmeta[base + t * 4 + 3] = ((o3 + off) << 16) | cc.w;
    g_bndcur[base + t * 4 + 0] = o0 + off;
    g_bndcur[base + t * 4 + 1] = o1 + off;
    g_bndcur[base + t * 4 + 2] = o2 + off;
    g_bndcur[base + t * 4 + 3] = o3 + off;
    gbar(&g_bars[3], K2G);

    // phase 3: CSR scatter
    if (gid < NBND) {
        int j = g_bndbin[gid];
        unsigned pos = atomicAdd(&g_bndcur[j], 1u);
        g_list[pos] = make_uint2(__float_as_uint(g_bndval[gid]), (unsigned)gid);
    }
}

// ================= k3: heavy pass (acc atomics + boundary partials) =========
__device__ __forceinline__ void main_one(float v, float xmin, float bs, float binw,
                                         const unsigned* __restrict__ bm) {
    int j = binof(v, xmin, bs);
    float offs = fmaxf(v - binlo(j, xmin, binw), 0.0f);
    unsigned long long pk = (1ULL << 48) | (unsigned long long)(offs * FXS);
    atomicAdd(&g_acc[j], pk);
    if ((bm[j >> 5] >> (j & 31)) & 1u) {
        unsigned m = __ldg(&g_bndmeta[j]);
        unsigned b0 = m >> 16, cnt = m & 0xFFFFu;
        for (unsigned q = b0; q < b0 + cnt; ++q) {
            uint2 e = __ldg(&g_list[q]);
            if (v < __uint_as_float(e.x))
                atomicAdd(&g_part[e.y], pk);
        }
    }
}

__global__ void __launch_bounds__(TPB) k3_main(const float* __restrict__ x, int n) {
    __shared__ unsigned bm[NB / 32];
    for (int i = threadIdx.x; i < NB / 32; i += TPB) bm[i] = g_bitmap[i];
    __syncthreads();
    float xmin = g_xminF, bs = g_bsF, binw = g_binwF;

    int tid = blockIdx.x * TPB + threadIdx.x;
    int stride = GRID3 * TPB;
    int n4 = n >> 2;
    const float4* x4 = (const float4*)x;
    for (int p = tid; p < n4; p += stride) {
        float4 v = __ldg(x4 + p);
        main_one(v.x, xmin, bs, binw, bm);
        main_one(v.y, xmin, bs, binw, bm);
        main_one(v.z, xmin, bs, binw, bm);
        main_one(v.w, xmin, bs, binw, bm);
    }
    int r = n & 3;
    if (tid < r) main_one(x[n - r + tid], xmin, bs, binw, bm);
}

// ================= k4: scan + eval + argmin (fused) =========================
__global__ void __launch_bounds__(1024, 1) k4_final(float* __restrict__ out, int n) {
    int t = threadIdx.x, b = blockIdx.x;
    int j = b * 1024 + t;
    float xmin = g_xminF, binw = g_binwF;

    unsigned long long a = g_acc[j];
    unsigned cnt = (unsigned)(a >> 48);
    double dx = (double)cnt * (double)binlo(j, xmin, binw) + (double)(a & PMASK) * FXSI;

    __shared__ unsigned shc[1024];
    __shared__ double   shd[1024];
    shc[t] = cnt; shd[t] = dx;
    __syncthreads();
    for (int off = 1; off < 1024; off <<= 1) {
        unsigned vc = (t >= off) ? shc[t - off] : 0u;
        double   vd = (t >= off) ? shd[t - off] : 0.0;
        __syncthreads();
        shc[t] += vc; shd[t] += vd;
        __syncthreads();
    }
    unsigned inc_c = shc[t];
    double   inc_x = shd[t];
    unsigned rel_c = inc_c - cnt;
    double   rel_x = inc_x - dx;
    if (t == 1023) { g_ptotc[b] = inc_c; g_ptotx[b] = inc_x; }
    gbar(&g_bars[4], K4G);

    __shared__ unsigned soffc;
    __shared__ double   soffx;
    if (t == 0) {
        unsigned oc = 0; double ox = 0.0;
        for (int q = 0; q < b; ++q) {
            oc += __ldcg(&g_ptotc[q]);
            ox += __ldcg(&g_ptotx[q]);
        }
        soffc = oc; soffx = ox;
        if (b == K4G - 1) g_totsx = ox + __ldcg(&g_ptotx[b]);
    }
    __syncthreads();
    g_pwcnt[j] = rel_c + soffc;
    g_pwsx[j]  = rel_x + soffx;
    gbar(&g_bars[5], K4G);

    // ---- eval: one warp per candidate ----
    int gw = b * 32 + (t >> 5);
    int lane = t & 31;
    if (gw < NCAND) {
        int cand = gw;
        float s = g_scale[cand], z = g_zp[cand];
        double dcnt = 0.0, dsx = 0.0;
        if (lane >= 1 && lane <= 15) {
            int id = cand * 15 + (lane - 1);
            int jj = g_bndbin[id];
            unsigned long long pp = __ldcg(&g_part[id]);
            unsigned pcnt = (unsigned)(pp >> 48);
            double poff = (double)(pp & PMASK) * FXSI;
            dcnt = (double)__ldcg(&g_pwcnt[jj]) + (double)pcnt;
            dsx  = __ldcg(&g_pwsx[jj])
                 + (double)pcnt * (double)binlo(jj, xmin, binw) + poff;
        } else if (lane == 16) {
            dcnt = (double)n;
            dsx  = __ldcg(&g_totsx);
        }
        __syncwarp();
        double ncnt = __shfl_down_sync(0xFFFFFFFFu, dcnt, 1);
        double nsx  = __shfl_down_sync(0xFFFFFFFFu, dsx, 1);
        double term = 0.0;
        if (lane < 16) {
            float v = ((float)lane - z) * s;
            double vd = (double)v;
            term = vd * vd * (ncnt - dcnt) - 2.0 * vd * (nsx - dsx);
        }
        #pragma unroll
        for (int off = 16; off > 0; off >>= 1)
            term += __shfl_xor_sync(0xFFFFFFFFu, term, off);
        if (lane == 0) g_scores[cand] = term;
    }
    gbar(&g_bars[6], K4G);

    // ---- argmin: block 0 ----
    if (b == 0) {
        double bsd = 1e300;
        int bi = NCAND;
        for (int c = t; c < NCAND; c += 1024) {
            double sv = __ldcg(&g_scores[c]);
            if (sv < bsd) { bsd = sv; bi = c; }
        }
        shd[t] = bsd;
        shc[t] = (unsigned)bi;
        __syncthreads();
        for (int off = 512; off > 0; off >>= 1) {
            if (t < off) {
                double so = shd[t + off];
                int    io = (int)shc[t + off];
                if (so < shd[t] || (so == shd[t] && io < (int)shc[t])) {
                    shd[t] = so; shc[t] = (unsigned)io;
                }
            }
            __syncthreads();
        }
        if (t == 0) {
            int idx = (int)shc[0];
            out[0] = g_cmin[idx];
            out[1] = g_cmax[idx];
        }
    }
}

// ---------------- launch ----------------
extern "C" void kernel_launch(void* const* d_in, const int* in_sizes, int n_in,
                              void* d_out, int out_size) {
    const float* x = (const float*)d_in[0];
    float* out = (float*)d_out;
    int n = in_sizes[0];

    k1_zero_minmax<<<GRID1, TPB>>>(x, n);
    k2_bnd<<<K2G, 256>>>();
    k3_main<<<GRID3, TPB>>>(x, n);
    k4_final<<<K4G, 1024>>>(out, n);
}

// round 9
// speedup vs baseline: 17.5744x; 1.0677x over previous
#include <cuda_runtime.h>
#include <cstdint>

// ---------------- constants ----------------
#define NCAND   1600
#define NBND    (NCAND * 15)        // 24000
#define NB      131072              // fine value bins
#define TPB     256
#define GRID1   592                 // k1 blocks
#define K2G     128                 // k2 blocks (resident -> grid barrier safe)
#define GRID3   888                 // k3 blocks (6/SM)
#define K4G     64                  // k4 blocks (resident, 2 bins/thread)
#define EPS_F32 1.1920928955078125e-07f
#define FXS     1099511627776.0f    // 2^40
#define FXSI    (1.0 / 1099511627776.0)
#define PMASK   0x0000FFFFFFFFFFFFULL

// ---------------- device state ----------------
__device__ unsigned g_bminenc[GRID1], g_bmaxenc[GRID1];
__device__ float    g_xminF, g_xmaxF, g_bsF, g_binwF;
__device__ float    g_scale[NCAND], g_zp[NCAND], g_cmin[NCAND], g_cmax[NCAND];
__device__ float    g_bndval[NBND];
__device__ int      g_bndbin[NBND];
__device__ unsigned g_bndcnt[NB];
__device__ unsigned g_bndmeta[NB];      // (csr_off << 16) | cnt
__device__ unsigned g_bndcur[NB];
__device__ uint2    g_list[NBND];       // {valbits, id}
__device__ unsigned g_bitmap[NB / 32];
__device__ __align__(16) unsigned long long g_acc[NB];
__device__ unsigned long long g_part[NBND];
__device__ unsigned g_pwcnt[NB];
__device__ double   g_pwsx[NB];
__device__ unsigned g_psum2[K2G];
__device__ unsigned g_ptotc[K4G];
__device__ double   g_ptotx[K4G];
__device__ double   g_totsx;
__device__ double   g_scores[NCAND];
__device__ unsigned g_bars[8];

// ---------------- helpers ----------------
__device__ __forceinline__ unsigned enc_f32(float f) {
    unsigned u = __float_as_uint(f);
    return (u & 0x80000000u) ? ~u : (u | 0x80000000u);
}
__device__ __forceinline__ float dec_f32(unsigned e) {
    unsigned u = (e & 0x80000000u) ? (e ^ 0x80000000u) : ~e;
    return __uint_as_float(u);
}
__device__ __forceinline__ int binof(float v, float xmin, float bs) {
    int j = (int)((v - xmin) * bs);
    j = j < 0 ? 0 : j;
    return j < NB ? j : (NB - 1);
}
__device__ __forceinline__ float binlo(int j, float xmin, float binw) {
    return __fmaf_rn((float)j, binw, xmin);
}
// software grid barrier — requires all gridDim blocks resident
__device__ __forceinline__ void gbar(unsigned* ctr, unsigned target) {
    __threadfence();
    __syncthreads();
    if (threadIdx.x == 0) {
        atomicAdd(ctr, 1u);
        while (*((volatile unsigned*)ctr) < target) {}
    }
    __syncthreads();
}
__device__ __forceinline__ void cand_params(int c, float x_min, float x_max,
                                            float& scale, float& zp,
                                            float& nmin, float& nmax) {
    float xrange = x_max - x_min;
    int i = c / 16 + 1;
    int j = c % 16;
    float fi = (float)i, zj = (float)j;
    float tmp_max   = __fmul_rn(__fdiv_rn(xrange, 100.0f), fi);
    float tmp_delta = __fdiv_rn(tmp_max, 15.0f);
    float zd = __fmul_rn(zj, tmp_delta);
    nmin = fmaxf(-zd, x_min);
    nmax = fminf(__fsub_rn(tmp_max, zd), x_max);
    float min_neg = fminf(nmin, 0.0f);
    float max_pos = fmaxf(nmax, 0.0f);
    scale = fmaxf(__fdiv_rn(__fsub_rn(max_pos, min_neg), 15.0f), EPS_F32);
    zp = fminf(fmaxf(0.0f - rintf(__fdiv_rn(min_neg, scale)), 0.0f), 15.0f);
}

// ================= k1: zero state + global min/max =================
__global__ void __launch_bounds__(TPB) k1_zero_minmax(const float* __restrict__ x, int n) {
    int tid = blockIdx.x * TPB + threadIdx.x;
    int stride = GRID1 * TPB;
    for (int i = tid; i < NB; i += stride) { g_acc[i] = 0ULL; g_bndcnt[i] = 0u; }
    for (int i = tid; i < NB / 32; i += stride) g_bitmap[i] = 0u;
    for (int i = tid; i < NBND; i += stride) g_part[i] = 0ULL;
    if (tid < 8) g_bars[tid] = 0u;

    float lmin = 3.4e38f, lmax = -3.4e38f;
    int n4 = n >> 2;
    const float4* x4 = (const float4*)x;
    for (int p = tid; p < n4; p += stride) {
        float4 v = __ldg(x4 + p);
        lmin = fminf(lmin, fminf(fminf(v.x, v.y), fminf(v.z, v.w)));
        lmax = fmaxf(lmax, fmaxf(fmaxf(v.x, v.y), fmaxf(v.z, v.w)));
    }
    int r = n & 3;
    if (tid < r) {
        float v = x[n - r + tid];
        lmin = fminf(lmin, v);
        lmax = fmaxf(lmax, v);
    }
    unsigned emin = __reduce_min_sync(0xFFFFFFFFu, enc_f32(lmin));
    unsigned emax = __reduce_max_sync(0xFFFFFFFFu, enc_f32(lmax));
    __shared__ unsigned smn[TPB / 32], smx[TPB / 32];
    int wid = threadIdx.x >> 5, lane = threadIdx.x & 31;
    if (lane == 0) { smn[wid] = emin; smx[wid] = emax; }
    __syncthreads();
    if (wid == 0) {
        unsigned a = (lane < TPB / 32) ? smn[lane] : 0xFFFFFFFFu;
        unsigned b = (lane < TPB / 32) ? smx[lane] : 0u;
        a = __reduce_min_sync(0xFFFFFFFFu, a);
        b = __reduce_max_sync(0xFFFFFFFFu, b);
        if (lane == 0) { g_bminenc[blockIdx.x] = a; g_bmaxenc[blockIdx.x] = b; }
    }
}

// ================= k2: minmax-reduce + candidates + boundary CSR ============
__global__ void __launch_bounds__(256) k2_bnd() {
    int t = threadIdx.x, b = blockIdx.x;
    int gid = b * 256 + t;

    // phase 0: block 0 reduces per-block minmax partials
    if (b == 0) {
        unsigned emin = 0xFFFFFFFFu, emax = 0u;
        for (int i = t; i < GRID1; i += 256) {
            emin = min(emin, g_bminenc[i]);
            emax = max(emax, g_bmaxenc[i]);
        }
        emin = __reduce_min_sync(0xFFFFFFFFu, emin);
        emax = __reduce_max_sync(0xFFFFFFFFu, emax);
        __shared__ unsigned smn[8], smx[8];
        int wid = t >> 5, lane = t & 31;
        if (lane == 0) { smn[wid] = emin; smx[wid] = emax; }
        __syncthreads();
        if (wid == 0) {
            unsigned a = (lane < 8) ? smn[lane] : 0xFFFFFFFFu;
            unsigned c = (lane < 8) ? smx[lane] : 0u;
            a = __reduce_min_sync(0xFFFFFFFFu, a);
            c = __reduce_max_sync(0xFFFFFFFFu, c);
            if (lane == 0) {
                float xmin = dec_f32(a), xmax = dec_f32(c);
                g_xminF = xmin; g_xmaxF = xmax;
                float range = xmax - xmin;
                g_bsF = (float)NB / range;
                g_binwF = range / (float)NB;
            }
        }
    }
    gbar(&g_bars[0], K2G);

    float xmin = g_xminF, xmax = g_xmaxF, bs = g_bsF;

    // phase 1: candidates + boundaries
    if (gid < NCAND) {
        float s, z, nm, nx;
        cand_params(gid, xmin, xmax, s, z, nm, nx);
        g_scale[gid] = s; g_zp[gid] = z; g_cmin[gid] = nm; g_cmax[gid] = nx;
    }
    if (gid < NBND) {
        int c = gid / 15, k = gid % 15 + 1;
        float s, z, nm, nx;
        cand_params(c, xmin, xmax, s, z, nm, nx);
        double bd = (double)s * ((double)k - (double)z - 0.5);
        float bf = (float)bd;
        int j = binof(bf, xmin, bs);
        g_bndval[gid] = bf;
        g_bndbin[gid] = j;
        atomicAdd(&g_bndcnt[j], 1u);
        atomicOr(&g_bitmap[j >> 5], 1u << (j & 31));
    }
    gbar(&g_bars[1], K2G);

    // phase 2a: per-partition scan (1024 bins / block, 4 per thread)
    int base = b * 1024;
    uint4 cc = *(const uint4*)&g_bndcnt[base + t * 4];
    unsigned ts = cc.x + cc.y + cc.z + cc.w;
    __shared__ unsigned sh[256];
    sh[t] = ts;
    __syncthreads();
    for (int off = 1; off < 256; off <<= 1) {
        unsigned v = (t >= off) ? sh[t - off] : 0u;
        __syncthreads();
        sh[t] += v;
        __syncthreads();
    }
    unsigned excl = sh[t] - ts;
    unsigned o0 = excl, o1 = o0 + cc.x, o2 = o1 + cc.y, o3 = o2 + cc.z;
    if (t == 255) g_psum2[b] = sh[255];
    gbar(&g_bars[2], K2G);

    // phase 2b: block offset + write meta/cursors
    __shared__ unsigned shoff;
    if (t == 0) {
        unsigned o = 0;
        for (int q = 0; q < b; ++q) o += __ldcg(&g_psum2[q]);
        shoff = o;
    }
    __syncthreads();
    unsigned off = shoff;
    g_bndmeta[base + t * 4 + 0] = ((o0 + off) << 16) | cc.x;
    g_bndmeta[base + t * 4 + 1] = ((o1 + off) << 16) | cc.y;
    g_bndmeta[base + t * 4 + 2] = ((o2 + off) << 16) | cc.z;
    g_bndmeta[base + t * 4 + 3] = ((o3 + off) << 16) | cc.w;
    g_bndcur[base + t * 4 + 0] = o0 + off;
    g_bndcur[base + t * 4 + 1] = o1 + off;
    g_bndcur[base + t * 4 + 2] = o2 + off;
    g_bndcur[base + t * 4 + 3] = o3 + off;
    gbar(&g_bars[3], K2G);

    // phase 3: CSR scatter
    if (gid < NBND) {
        int j = g_bndbin[gid];
        unsigned pos = atomicAdd(&g_bndcur[j], 1u);
        g_list[pos] = make_uint2(__float_as_uint(g_bndval[gid]), (unsigned)gid);
    }
}

// ================= k3: heavy pass (acc atomics + boundary partials) =========
__device__ __forceinline__ void main_one(float v, float xmin, float bs, float binw,
                                         const unsigned* __restrict__ bm) {
    int j = binof(v, xmin, bs);
    float offs = fmaxf(v - binlo(j, xmin, binw), 0.0f);
    unsigned long long pk = (1ULL << 48) | (unsigned long long)(offs * FXS);
    atomicAdd(&g_acc[j], pk);
    if ((bm[j >> 5] >> (j & 31)) & 1u) {
        unsigned m = __ldg(&g_bndmeta[j]);
        unsigned b0 = m >> 16, cnt = m & 0xFFFFu;
        for (unsigned q = b0; q < b0 + cnt; ++q) {
            uint2 e = __ldg(&g_list[q]);
            if (v < __uint_as_float(e.x))
                atomicAdd(&g_part[e.y], pk);
        }
    }
}

__global__ void __launch_bounds__(TPB) k3_main(const float* __restrict__ x, int n) {
    __shared__ unsigned bm[NB / 32];
    for (int i = threadIdx.x; i < NB / 32; i += TPB) bm[i] = g_bitmap[i];
    __syncthreads();
    float xmin = g_xminF, bs = g_bsF, binw = g_binwF;

    int tid = blockIdx.x * TPB + threadIdx.x;
    int stride = GRID3 * TPB;
    int n4 = n >> 2;
    const float4* x4 = (const float4*)x;
    for (int p = tid; p < n4; p += stride) {
        float4 v = __ldg(x4 + p);
        main_one(v.x, xmin, bs, binw, bm);
        main_one(v.y, xmin, bs, binw, bm);
        main_one(v.z, xmin, bs, binw, bm);
        main_one(v.w, xmin, bs, binw, bm);
    }
    int r = n & 3;
    if (tid < r) main_one(x[n - r + tid], xmin, bs, binw, bm);
}

// ================= k4: shuffle-scan + eval + argmin (rebuilt) ===============
__global__ void __launch_bounds__(1024, 1) k4_final(float* __restrict__ out, int n) {
    int t = threadIdx.x, b = blockIdx.x;
    int lane = t & 31, wid = t >> 5;
    float xmin = g_xminF, binw = g_binwF;

    __shared__ unsigned swc[32];
    __shared__ double   swx[32];
    __shared__ unsigned sbc;
    __shared__ double   sbx;
    __shared__ unsigned shc[1024];   // argmin (block 0)
    __shared__ double   shd[1024];

    // ---- decode 2 bins/thread ----
    int j0 = (b * 1024 + t) * 2;
    ulonglong2 aa = *(const ulonglong2*)&g_acc[j0];
    unsigned c0 = (unsigned)(aa.x >> 48);
    unsigned c1 = (unsigned)(aa.y >> 48);
    double dx0 = (double)c0 * (double)binlo(j0,     xmin, binw) + (double)(aa.x & PMASK) * FXSI;
    double dx1 = (double)c1 * (double)binlo(j0 + 1, xmin, binw) + (double)(aa.y & PMASK) * FXSI;
    unsigned tc = c0 + c1;
    double   tx = dx0 + dx1;

    // ---- warp inclusive shuffle scan (fixed order) ----
    unsigned ic = tc; double ix = tx;
    #pragma unroll
    for (int off = 1; off < 32; off <<= 1) {
        unsigned uc = __shfl_up_sync(0xFFFFFFFFu, ic, off);
        double   ux = __shfl_up_sync(0xFFFFFFFFu, ix, off);
        if (lane >= off) { ic += uc; ix += ux; }
    }
    if (lane == 31) { swc[wid] = ic; swx[wid] = ix; }
    __syncthreads();
    // ---- warp 0 scans the 32 warp totals ----
    if (wid == 0) {
        unsigned wc = swc[lane]; double wx = swx[lane];
        unsigned jc = wc; double jx = wx;
        #pragma unroll
        for (int off = 1; off < 32; off <<= 1) {
            unsigned uc = __shfl_up_sync(0xFFFFFFFFu, jc, off);
            double   ux = __shfl_up_sync(0xFFFFFFFFu, jx, off);
            if (lane >= off) { jc += uc; jx += ux; }
        }
        swc[lane] = jc - wc;  // exclusive warp offset
        swx[lane] = jx - wx;
        if (lane == 31) { g_ptotc[b] = jc; g_ptotx[b] = jx; }
    }
    __syncthreads();
    unsigned exlc = (ic - tc) + swc[wid];   // block-relative exclusive prefix
    double   exlx = (ix - tx) + swx[wid];
    gbar(&g_bars[4], K4G);

    // ---- cross-block exclusive offsets: warp 0, pairwise shuffle scan -------
    if (wid == 0) {
        unsigned e0c = __ldcg(&g_ptotc[2 * lane]);
        unsigned e1c = __ldcg(&g_ptotc[2 * lane + 1]);
        double   e0x = __ldcg(&g_ptotx[2 * lane]);
        double   e1x = __ldcg(&g_ptotx[2 * lane + 1]);
        unsigned pc = e0c + e1c; double px = e0x + e1x;
        unsigned jc = pc; double jx = px;
        #pragma unroll
        for (int off = 1; off < 32; off <<= 1) {
            unsigned uc = __shfl_up_sync(0xFFFFFFFFu, jc, off);
            double   ux = __shfl_up_sync(0xFFFFFFFFu, jx, off);
            if (lane >= off) { jc += uc; jx += ux; }
        }
        unsigned pexc = jc - pc; double pexx = jx - px;   // excl before pair 2*lane
        if (b == 0 && lane == 31) g_totsx = jx;           // global total
        int pl = b >> 1;
        unsigned bc = __shfl_sync(0xFFFFFFFFu, pexc, pl);
        double   bx = __shfl_sync(0xFFFFFFFFu, pexx, pl);
        unsigned ac = __shfl_sync(0xFFFFFFFFu, e0c, pl);
        double   ax = __shfl_sync(0xFFFFFFFFu, e0x, pl);
        if (b & 1) { bc += ac; bx += ax; }
        if (lane == 0) { sbc = bc; sbx = bx; }
    }
    __syncthreads();
    unsigned basec = sbc + exlc;
    double   basex = sbx + exlx;
    g_pwcnt[j0]     = basec;
    g_pwsx[j0]      = basex;
    g_pwcnt[j0 + 1] = basec + c0;
    g_pwsx[j0 + 1]  = basex + dx0;
    gbar(&g_bars[5], K4G);

    // ---- eval: one warp per candidate (64*32 = 2048 warps >= 1600) ----
    int gw = b * 32 + wid;
    if (gw < NCAND) {
        int cand = gw;
        float s = g_scale[cand], z = g_zp[cand];
        double dcnt = 0.0, dsx = 0.0;
        if (lane >= 1 && lane <= 15) {
            int id = cand * 15 + (lane - 1);
            int jj = g_bndbin[id];
            unsigned long long pp = __ldcg(&g_part[id]);
            unsigned pcnt = (unsigned)(pp >> 48);
            double poff = (double)(pp & PMASK) * FXSI;
            dcnt = (double)__ldcg(&g_pwcnt[jj]) + (double)pcnt;
            dsx  = __ldcg(&g_pwsx[jj])
                 + (double)pcnt * (double)binlo(jj, xmin, binw) + poff;
        } else if (lane == 16) {
            dcnt = (double)n;
            dsx  = __ldcg(&g_totsx);
        }
        __syncwarp();
        double ncnt = __shfl_down_sync(0xFFFFFFFFu, dcnt, 1);
        double nsx  = __shfl_down_sync(0xFFFFFFFFu, dsx, 1);
        double term = 0.0;
        if (lane < 16) {
            float v = ((float)lane - z) * s;
            double vd = (double)v;
            term = vd * vd * (ncnt - dcnt) - 2.0 * vd * (nsx - dsx);
        }
        #pragma unroll
        for (int off = 16; off > 0; off >>= 1)
            term += __shfl_xor_sync(0xFFFFFFFFu, term, off);
        if (lane == 0) g_scores[cand] = term;
    }
    gbar(&g_bars[6], K4G);

    // ---- argmin: block 0 ----
    if (b == 0) {
        double bsd = 1e300;
        int bi = NCAND;
        for (int c = t; c < NCAND; c += 1024) {
            double sv = __ldcg(&g_scores[c]);
            if (sv < bsd) { bsd = sv; bi = c; }
        }
        shd[t] = bsd;
        shc[t] = (unsigned)bi;
        __syncthreads();
        for (int off = 512; off > 0; off >>= 1) {
            if (t < off) {
                double so = shd[t + off];
                int    io = (int)shc[t + off];
                if (so < shd[t] || (so == shd[t] && io < (int)shc[t])) {
                    shd[t] = so; shc[t] = (unsigned)io;
                }
            }
            __syncthreads();
        }
        if (t == 0) {
            int idx = (int)shc[0];
            out[0] = g_cmin[idx];
            out[1] = g_cmax[idx];
        }
    }
}

// ---------------- launch ----------------
extern "C" void kernel_launch(void* const* d_in, const int* in_sizes, int n_in,
                              void* d_out, int out_size) {
    const float* x = (const float*)d_in[0];
    float* out = (float*)d_out;
    int n = in_sizes[0];

    k1_zero_minmax<<<GRID1, TPB>>>(x, n);
    k2_bnd<<<K2G, 256>>>();
    k3_main<<<GRID3, TPB>>>(x, n);
    k4_final<<<K4G, 1024>>>(out, n);
}